// round 12
// baseline (speedup 1.0000x reference)
#include <cuda_runtime.h>

#define NN 50000
#define EE 800000
#define BB 64

// ---------------- all arguments in one by-value struct ----------------
struct KParams {
    int phase;
    const float* x; const int* ei; const int* batch;
    const float *W1, *a1s, *a1d, *b1;
    const float *W2, *a2s, *a2d, *b2;
    const float *W3, *a3s, *a3d, *b3;
    const float *W4, *a4s, *a4d, *b4;
    const float *Wc1, *bc1, *Wc2, *bc2;
    float *recon, *latent, *pred;
};

// ---------------- device scratch (~4.6 MB) ----------------
__device__ unsigned short g_csr[EE];     // send ids grouped by recv (N<65536)
__device__ int    g_off[NN + 1];         // CSR offsets
__device__ int    g_deg[NN];             // histogram / scatter cursor
__device__ float4 g_pkA[NN];             // (x0,x1,x2,hs1); later (h4_0..2,hs4)
__device__ float4 g_pkB[NN];             // (c0,c1,c2,hs2)
__device__ float  g_hsA[NN];             // latent-based src scalars (L3)
__device__ float  g_hdA[NN];             // dst scalars (L1, then L3)
__device__ float  g_hdB[NN];             // dst scalars (L2, then L4)
__device__ int    g_bsum[256];           // scan block sums
__device__ float  g_pool[BB * 64];
__device__ int    g_cnt[BB];
__device__ int    g_flags[2];            // [0] ei int64?  [1] batch int64?
__device__ float  g_w1s[3], g_w1d[3];
__device__ float  g_w2s[128], g_w2d[128];
__device__ float  g_w3s[64], g_w3d[64];

__device__ __forceinline__ float lrelu_exp(float e) {
    e = e > 0.f ? e : 0.2f * e;
    return __expf(e);
}

// ---------------- the single kernel, phase-dispatched ----------------
// P0 init+detect+proj (197)   P1 hist (3125)     P2 scan1 (196)
// P3 scan2 (1)                P4 scan3+dots1+pack (196)
// P5 scatter (3125)           P6 aggL1+dots2 (6250)
// P7 aggL2 reg-staged + pool + dots3 (6250)
// P8 aggL3 prefetched + dots4 (6250)
// P9 aggL4->recon + classifier (6258)
__global__ void __launch_bounds__(256) gat_kernel(KParams p) {
    __shared__ float sf[1088];
    int* si = (int*)sf;
    const int t = threadIdx.x;
    const int b = blockIdx.x;
    const int ph = p.phase;

    if (ph == 0) {                       // ---- init + detect + proj ----
        if (b < 196) {
            int i = b * 256 + t;
            if (i < NN) g_deg[i] = 0;
            if (i < BB * 64) g_pool[i] = 0.f;
            if (i < BB) g_cnt[i] = 0;
            if (b == 0 && t < 64) {
                int lane = t & 31;
                int nz = 0;
                if (t < 32) {
                    for (int k = lane; k < 128; k += 32) nz |= p.ei[2 * k + 1];
                } else {
                    for (int k = lane; k < 128; k += 32) nz |= p.batch[NN - 256 + 2 * k + 1];
                }
                #pragma unroll
                for (int o = 16; o; o >>= 1) nz |= __shfl_xor_sync(0xffffffffu, nz, o);
                if (lane == 0) g_flags[t < 32 ? 0 : 1] = (nz == 0) ? 1 : 0;
            }
        } else {                         // block 196: projections
            if (t < 128) {
                float s = 0.f, d = 0.f;
                for (int k = 0; k < 64; k++) {
                    float w = p.W2[t * 64 + k];
                    s = fmaf(w, p.a2s[k], s);
                    d = fmaf(w, p.a2d[k], d);
                }
                g_w2s[t] = s; g_w2d[t] = d;
            } else if (t < 192) {
                int i = t - 128;
                float s = 0.f, d = 0.f;
                for (int k = 0; k < 128; k++) {
                    float w = p.W3[i * 128 + k];
                    s = fmaf(w, p.a3s[k], s);
                    d = fmaf(w, p.a3d[k], d);
                }
                g_w3s[i] = s; g_w3d[i] = d;
            } else if (t < 195) {
                int i = t - 192;
                float s = 0.f;
                for (int k = 0; k < 128; k++) s = fmaf(p.W1[i * 128 + k], p.a1s[k], s);
                g_w1s[i] = s;
            } else if (t < 198) {
                int i = t - 195;
                float d = 0.f;
                for (int k = 0; k < 128; k++) d = fmaf(p.W1[i * 128 + k], p.a1d[k], d);
                g_w1d[i] = d;
            }
        }
    } else if (ph == 1) {                // ---- degree histogram ----
        int e = b * 256 + t;
        if (e < EE) {
            int r = g_flags[0] ? (int)((const long long*)p.ei)[(size_t)EE + e]
                               : p.ei[EE + e];
            atomicAdd(&g_deg[r], 1);
        }
    } else if (ph == 2) {                // ---- scan part 1 ----
        int i = b * 256 + t;
        int v = (i < NN) ? g_deg[i] : 0;
        si[t] = v;
        __syncthreads();
        #pragma unroll
        for (int d = 1; d < 256; d <<= 1) {
            int tv = (t >= d) ? si[t - d] : 0;
            __syncthreads();
            si[t] += tv;
            __syncthreads();
        }
        if (i < NN) g_off[i] = si[t] - v;
        if (t == 255) g_bsum[b] = si[255];
    } else if (ph == 3) {                // ---- scan part 2 ----
        int v = (t < 196) ? g_bsum[t] : 0;
        si[t] = v;
        __syncthreads();
        #pragma unroll
        for (int d = 1; d < 256; d <<= 1) {
            int tv = (t >= d) ? si[t - d] : 0;
            __syncthreads();
            si[t] += tv;
            __syncthreads();
        }
        if (t < 196) g_bsum[t] = si[t] - v;
    } else if (ph == 4) {                // ---- scan3 + dots1 + pack x ----
        int i = b * 256 + t;
        if (i < NN) {
            g_off[i] += g_bsum[b];
            g_deg[i] = 0;
            float x0 = p.x[i * 3 + 0], x1 = p.x[i * 3 + 1], x2 = p.x[i * 3 + 2];
            float hs = x0 * g_w1s[0] + x1 * g_w1s[1] + x2 * g_w1s[2];
            g_pkA[i] = make_float4(x0, x1, x2, hs);
            g_hdA[i] = x0 * g_w1d[0] + x1 * g_w1d[1] + x2 * g_w1d[2];
        }
        if (i == 0) g_off[NN] = EE;
    } else if (ph == 5) {                // ---- scatter to CSR ----
        int e = b * 256 + t;
        if (e < EE) {
            int r, s;
            if (g_flags[0]) {
                r = (int)((const long long*)p.ei)[(size_t)EE + e];
                s = (int)((const long long*)p.ei)[e];
            } else {
                r = p.ei[EE + e];
                s = p.ei[e];
            }
            int pos = g_off[r] + atomicAdd(&g_deg[r], 1);
            g_csr[pos] = (unsigned short)s;
        }
    } else if (ph == 6) {                // ---- aggL1 -> c, + inline dots2, pack ----
        int gw = (b * 256 + t) >> 5;
        int lane = t & 31;
        if (gw < NN) {
            int beg = g_off[gw], end = g_off[gw + 1];
            float hdi = g_hdA[gw];
            float s = 0.f, a0 = 0.f, a1 = 0.f, a2 = 0.f;
            for (int j = beg + lane; j < end; j += 32) {
                int sn = g_csr[j];
                float4 pk = g_pkA[sn];               // one 16B gather: x + hs
                float w = lrelu_exp(pk.w + hdi);
                s += w;
                a0 = fmaf(w, pk.x, a0);
                a1 = fmaf(w, pk.y, a1);
                a2 = fmaf(w, pk.z, a2);
            }
            #pragma unroll
            for (int o = 16; o; o >>= 1) {
                s  += __shfl_xor_sync(0xffffffffu, s, o);
                a0 += __shfl_xor_sync(0xffffffffu, a0, o);
                a1 += __shfl_xor_sync(0xffffffffu, a1, o);
                a2 += __shfl_xor_sync(0xffffffffu, a2, o);
            }
            float4 pks = g_pkA[gw];                  // self loop
            float ws = lrelu_exp(pks.w + hdi);
            s += ws;
            a0 = fmaf(ws, pks.x, a0);
            a1 = fmaf(ws, pks.y, a1);
            a2 = fmaf(ws, pks.z, a2);
            float inv = 1.f / s;
            float c0 = a0 * inv, c1 = a1 * inv, c2 = a2 * inv;
            // inline dots2: z = relu(c@W1+b1), hs2 = z.w2s, hd2 = z.w2d
            int k0 = lane * 4;
            float4 w0 = *(const float4*)&p.W1[0 * 128 + k0];
            float4 w1 = *(const float4*)&p.W1[1 * 128 + k0];
            float4 w2 = *(const float4*)&p.W1[2 * 128 + k0];
            float4 bb = *(const float4*)&p.b1[k0];
            float z0 = fmaxf(fmaf(c0, w0.x, fmaf(c1, w1.x, fmaf(c2, w2.x, bb.x))), 0.f);
            float z1 = fmaxf(fmaf(c0, w0.y, fmaf(c1, w1.y, fmaf(c2, w2.y, bb.y))), 0.f);
            float z2 = fmaxf(fmaf(c0, w0.z, fmaf(c1, w1.z, fmaf(c2, w2.z, bb.z))), 0.f);
            float z3 = fmaxf(fmaf(c0, w0.w, fmaf(c1, w1.w, fmaf(c2, w2.w, bb.w))), 0.f);
            float4 vs = *(const float4*)&g_w2s[k0];
            float4 vd = *(const float4*)&g_w2d[k0];
            float ss = z0 * vs.x + z1 * vs.y + z2 * vs.z + z3 * vs.w;
            float dd = z0 * vd.x + z1 * vd.y + z2 * vd.z + z3 * vd.w;
            #pragma unroll
            for (int o = 16; o; o >>= 1) {
                ss += __shfl_xor_sync(0xffffffffu, ss, o);
                dd += __shfl_xor_sync(0xffffffffu, dd, o);
            }
            if (lane == 0) {
                g_pkB[gw] = make_float4(c0, c1, c2, ss);
                g_hdB[gw] = dd;
            }
        }
    } else if (ph == 7) {                // ---- fused L2 (reg-staged) + pool + dots3 ----
        int gw = (b * 256 + t) >> 5;
        int wid = (t >> 5) & 7;
        int lane = t & 31;
        if (gw < NN) {
            float* zsh = &sf[wid * 128];
            int beg = g_off[gw], end = g_off[gw + 1];
            float hdi = g_hdB[gw];
            int k0 = lane * 4;
            float4 w0 = *(const float4*)&p.W1[0 * 128 + k0];
            float4 w1 = *(const float4*)&p.W1[1 * 128 + k0];
            float4 w2 = *(const float4*)&p.W1[2 * 128 + k0];
            float4 bb = *(const float4*)&p.b1[k0];
            float s = 0.f;
            float acx = 0.f, acy = 0.f, acz = 0.f, acw = 0.f;
            for (int base = beg; base < end; base += 32) {
                int n = end - base; n = n < 32 ? n : 32;
                int sn_l = g_csr[base + (lane < n ? lane : 0)];   // coalesced stage
                float4 pk_l = g_pkB[sn_l];                        // parallel gather MLP=32
                for (int jj = 0; jj < n; jj++) {
                    float px = __shfl_sync(0xffffffffu, pk_l.x, jj);
                    float py = __shfl_sync(0xffffffffu, pk_l.y, jj);
                    float pz = __shfl_sync(0xffffffffu, pk_l.z, jj);
                    float pw = __shfl_sync(0xffffffffu, pk_l.w, jj);
                    float w = lrelu_exp(pw + hdi);
                    s += w;
                    float z0 = fmaxf(fmaf(px, w0.x, fmaf(py, w1.x, fmaf(pz, w2.x, bb.x))), 0.f);
                    float z1 = fmaxf(fmaf(px, w0.y, fmaf(py, w1.y, fmaf(pz, w2.y, bb.y))), 0.f);
                    float z2 = fmaxf(fmaf(px, w0.z, fmaf(py, w1.z, fmaf(pz, w2.z, bb.z))), 0.f);
                    float z3 = fmaxf(fmaf(px, w0.w, fmaf(py, w1.w, fmaf(pz, w2.w, bb.w))), 0.f);
                    acx = fmaf(w, z0, acx);
                    acy = fmaf(w, z1, acy);
                    acz = fmaf(w, z2, acz);
                    acw = fmaf(w, z3, acw);
                }
            }
            {   // self loop
                float4 pk = g_pkB[gw];
                float w = lrelu_exp(pk.w + hdi);
                s += w;
                float z0 = fmaxf(fmaf(pk.x, w0.x, fmaf(pk.y, w1.x, fmaf(pk.z, w2.x, bb.x))), 0.f);
                float z1 = fmaxf(fmaf(pk.x, w0.y, fmaf(pk.y, w1.y, fmaf(pk.z, w2.y, bb.y))), 0.f);
                float z2 = fmaxf(fmaf(pk.x, w0.z, fmaf(pk.y, w1.z, fmaf(pk.z, w2.z, bb.z))), 0.f);
                float z3 = fmaxf(fmaf(pk.x, w0.w, fmaf(pk.y, w1.w, fmaf(pk.z, w2.w, bb.w))), 0.f);
                acx = fmaf(w, z0, acx);
                acy = fmaf(w, z1, acy);
                acz = fmaf(w, z2, acz);
                acw = fmaf(w, z3, acw);
            }
            float inv = 1.f / s;                     // uniform across lanes
            zsh[k0 + 0] = acx * inv;
            zsh[k0 + 1] = acy * inv;
            zsh[k0 + 2] = acz * inv;
            zsh[k0 + 3] = acw * inv;
            __syncwarp();
            int m = lane * 2;
            float o0 = p.b2[m], o1 = p.b2[m + 1];
            #pragma unroll 8
            for (int k = 0; k < 128; k++) {
                float zk = zsh[k];
                float2 w = *(const float2*)&p.W2[k * 64 + m];
                o0 = fmaf(zk, w.x, o0);
                o1 = fmaf(zk, w.y, o1);
            }
            p.latent[(size_t)gw * 64 + m]     = o0;
            p.latent[(size_t)gw * 64 + m + 1] = o1;
            // pooling (latent is in registers)
            int bi = g_flags[1] ? (int)((const long long*)p.batch)[gw] : p.batch[gw];
            atomicAdd(&g_pool[bi * 64 + m], o0);
            atomicAdd(&g_pool[bi * 64 + m + 1], o1);
            if (lane == 0) atomicAdd(&g_cnt[bi], 1);
            // inline dots3
            float ss = o0 * g_w3s[m] + o1 * g_w3s[m + 1];
            float dd = o0 * g_w3d[m] + o1 * g_w3d[m + 1];
            #pragma unroll
            for (int o = 16; o; o >>= 1) {
                ss += __shfl_xor_sync(0xffffffffu, ss, o);
                dd += __shfl_xor_sync(0xffffffffu, dd, o);
            }
            if (lane == 0) { g_hsA[gw] = ss; g_hdA[gw] = dd; }
        }
    } else if (ph == 8) {                // ---- fused L3 (prefetched) + dots4, pack ----
        int gw = (b * 256 + t) >> 5;
        int wid = (t >> 5) & 7;
        int lane = t & 31;
        if (gw < NN) {
            float* dsh = &sf[wid * 64];
            int beg = g_off[gw], end = g_off[gw + 1];
            float hdi = g_hdA[gw];
            int m = lane * 2;
            float s = 0.f, ax = 0.f, ay = 0.f;
            for (int base = beg; base < end; base += 32) {
                int n = end - base; n = n < 32 ? n : 32;
                int idx = base + (lane < n ? lane : 0);
                int sn_l = g_csr[idx];               // coalesced stage
                float hs_l = g_hsA[sn_l];            // parallel gather
                int sn_cur = __shfl_sync(0xffffffffu, sn_l, 0);
                float2 vcur = *(const float2*)&p.latent[(size_t)sn_cur * 64 + m];
                for (int jj = 0; jj < n; jj++) {
                    float2 vnext = make_float2(0.f, 0.f);
                    if (jj + 1 < n) {                // register prefetch (MLP=2)
                        int snn = __shfl_sync(0xffffffffu, sn_l, jj + 1);
                        vnext = *(const float2*)&p.latent[(size_t)snn * 64 + m];
                    }
                    float hsv = __shfl_sync(0xffffffffu, hs_l, jj);
                    float w = lrelu_exp(hsv + hdi);
                    s += w;
                    ax = fmaf(w, vcur.x, ax);
                    ay = fmaf(w, vcur.y, ay);
                    vcur = vnext;
                }
            }
            {   // self loop
                float w = lrelu_exp(g_hsA[gw] + hdi);
                float2 v = *(const float2*)&p.latent[(size_t)gw * 64 + m];
                s += w;
                ax = fmaf(w, v.x, ax);
                ay = fmaf(w, v.y, ay);
            }
            float inv = 1.f / s;
            dsh[m] = ax * inv;
            dsh[m + 1] = ay * inv;
            __syncwarp();
            int k0 = lane * 4;
            float4 acc = *(const float4*)&p.b3[k0];
            for (int i = 0; i < 64; i++) {
                float di = dsh[i];
                float4 w = *(const float4*)&p.W3[i * 128 + k0];
                acc.x = fmaf(di, w.x, acc.x);
                acc.y = fmaf(di, w.y, acc.y);
                acc.z = fmaf(di, w.z, acc.z);
                acc.w = fmaf(di, w.w, acc.w);
            }
            acc.x = fmaxf(acc.x, 0.f); acc.y = fmaxf(acc.y, 0.f);
            acc.z = fmaxf(acc.z, 0.f); acc.w = fmaxf(acc.w, 0.f);
            float a0 = acc.x * p.W4[(k0 + 0) * 3 + 0] + acc.y * p.W4[(k0 + 1) * 3 + 0]
                     + acc.z * p.W4[(k0 + 2) * 3 + 0] + acc.w * p.W4[(k0 + 3) * 3 + 0];
            float a1 = acc.x * p.W4[(k0 + 0) * 3 + 1] + acc.y * p.W4[(k0 + 1) * 3 + 1]
                     + acc.z * p.W4[(k0 + 2) * 3 + 1] + acc.w * p.W4[(k0 + 3) * 3 + 1];
            float a2 = acc.x * p.W4[(k0 + 0) * 3 + 2] + acc.y * p.W4[(k0 + 1) * 3 + 2]
                     + acc.z * p.W4[(k0 + 2) * 3 + 2] + acc.w * p.W4[(k0 + 3) * 3 + 2];
            #pragma unroll
            for (int o = 16; o; o >>= 1) {
                a0 += __shfl_xor_sync(0xffffffffu, a0, o);
                a1 += __shfl_xor_sync(0xffffffffu, a1, o);
                a2 += __shfl_xor_sync(0xffffffffu, a2, o);
            }
            if (lane == 0) {
                float hs4 = a0 * p.a4s[0] + a1 * p.a4s[1] + a2 * p.a4s[2];
                g_pkA[gw] = make_float4(a0, a1, a2, hs4);
                g_hdB[gw] = a0 * p.a4d[0] + a1 * p.a4d[1] + a2 * p.a4d[2];
            }
        }
    } else if (ph == 9) {                // ---- aggL4 -> recon, + classifier tail ----
        int lane = t & 31;
        if (b < 6250) {
            int gw = (b * 256 + t) >> 5;
            if (gw < NN) {
                int beg = g_off[gw], end = g_off[gw + 1];
                float hdi = g_hdB[gw];
                float s = 0.f, a0 = 0.f, a1 = 0.f, a2 = 0.f;
                for (int j = beg + lane; j < end; j += 32) {
                    int sn = g_csr[j];
                    float4 pk = g_pkA[sn];           // one 16B gather: h4 + hs4
                    float w = lrelu_exp(pk.w + hdi);
                    s += w;
                    a0 = fmaf(w, pk.x, a0);
                    a1 = fmaf(w, pk.y, a1);
                    a2 = fmaf(w, pk.z, a2);
                }
                #pragma unroll
                for (int o = 16; o; o >>= 1) {
                    s  += __shfl_xor_sync(0xffffffffu, s, o);
                    a0 += __shfl_xor_sync(0xffffffffu, a0, o);
                    a1 += __shfl_xor_sync(0xffffffffu, a1, o);
                    a2 += __shfl_xor_sync(0xffffffffu, a2, o);
                }
                float4 pks = g_pkA[gw];
                float ws = lrelu_exp(pks.w + hdi);
                s += ws;
                a0 = fmaf(ws, pks.x, a0);
                a1 = fmaf(ws, pks.y, a1);
                a2 = fmaf(ws, pks.z, a2);
                float inv = 1.f / s;
                if (lane == 0) {
                    p.recon[gw * 3 + 0] = a0 * inv + p.b4[0];
                    p.recon[gw * 3 + 1] = a1 * inv + p.b4[1];
                    p.recon[gw * 3 + 2] = a2 * inv + p.b4[2];
                }
            }
        } else {                         // classifier: blocks 6250..6257
            int wid = t >> 5;
            int g = (b - 6250) * 8 + wid;
            if (g < BB) {
                float* pp = &sf[wid * 64];
                float invc = 1.f / fmaxf((float)g_cnt[g], 1.f);
                pp[lane] = g_pool[g * 64 + lane] * invc;
                pp[lane + 32] = g_pool[g * 64 + lane + 32] * invc;
                __syncwarp();
                float z = p.bc1[lane];
                #pragma unroll 8
                for (int d = 0; d < 64; d++) z = fmaf(pp[d], p.Wc1[d * 32 + lane], z);
                z = fmaxf(z, 0.f);
                float o0 = z * p.Wc2[lane * 2 + 0];
                float o1 = z * p.Wc2[lane * 2 + 1];
                #pragma unroll
                for (int o = 16; o; o >>= 1) {
                    o0 += __shfl_xor_sync(0xffffffffu, o0, o);
                    o1 += __shfl_xor_sync(0xffffffffu, o1, o);
                }
                if (lane == 0) {
                    p.pred[g * 2 + 0] = o0 + p.bc2[0];
                    p.pred[g * 2 + 1] = o1 + p.bc2[1];
                }
            }
        }
    }
}

// ---------------- launcher ----------------
extern "C" void kernel_launch(void* const* d_in, const int* in_sizes, int n_in,
                              void* d_out, int out_size) {
    KParams p;
    p.x     = (const float*)d_in[0];
    p.ei    = (const int*)d_in[1];
    p.batch = (const int*)d_in[2];
    p.W1 = (const float*)d_in[3];  p.a1s = (const float*)d_in[4];
    p.a1d = (const float*)d_in[5]; p.b1  = (const float*)d_in[6];
    p.W2 = (const float*)d_in[7];  p.a2s = (const float*)d_in[8];
    p.a2d = (const float*)d_in[9]; p.b2  = (const float*)d_in[10];
    p.W3 = (const float*)d_in[11]; p.a3s = (const float*)d_in[12];
    p.a3d = (const float*)d_in[13];p.b3  = (const float*)d_in[14];
    p.W4 = (const float*)d_in[15]; p.a4s = (const float*)d_in[16];
    p.a4d = (const float*)d_in[17];p.b4  = (const float*)d_in[18];
    p.Wc1 = (const float*)d_in[19];p.bc1 = (const float*)d_in[20];
    p.Wc2 = (const float*)d_in[21];p.bc2 = (const float*)d_in[22];
    p.recon  = (float*)d_out;
    p.latent = (float*)d_out + 150000;
    p.pred   = (float*)d_out + 150000 + 3200000;

    const int nGrid = (NN + 255) / 256;          // 196
    const int eGrid = (EE + 255) / 256;          // 3125
    const int wGrid = (NN * 32 + 255) / 256;     // 6250

    p.phase = 0;  gat_kernel<<<nGrid + 1, 256>>>(p);  // init + detect + proj
    p.phase = 1;  gat_kernel<<<eGrid, 256>>>(p);      // histogram
    p.phase = 2;  gat_kernel<<<nGrid, 256>>>(p);      // scan (block)
    p.phase = 3;  gat_kernel<<<1, 256>>>(p);          // scan (sums)
    p.phase = 4;  gat_kernel<<<nGrid, 256>>>(p);      // scan (add) + dots1 + pack
    p.phase = 5;  gat_kernel<<<eGrid, 256>>>(p);      // scatter -> CSR
    p.phase = 6;  gat_kernel<<<wGrid, 256>>>(p);      // L1 agg + dots2
    p.phase = 7;  gat_kernel<<<wGrid, 256>>>(p);      // L2 fused + pool + dots3
    p.phase = 8;  gat_kernel<<<wGrid, 256>>>(p);      // L3 fused + dots4
    p.phase = 9;  gat_kernel<<<wGrid + 8, 256>>>(p);  // L4 agg -> recon + cls
}

// round 13
// speedup vs baseline: 1.0536x; 1.0536x over previous
#include <cuda_runtime.h>

#define NN 50000
#define EE 800000
#define BB 64

// ---------------- all arguments in one by-value struct ----------------
struct KParams {
    int phase;
    const float* x; const int* ei; const int* batch;
    const float *W1, *a1s, *a1d, *b1;
    const float *W2, *a2s, *a2d, *b2;
    const float *W3, *a3s, *a3d, *b3;
    const float *W4, *a4s, *a4d, *b4;
    const float *Wc1, *bc1, *Wc2, *bc2;
    float *recon, *latent, *pred;
};

// ---------------- device scratch (~17 MB; single kernel function) ----------------
__device__ unsigned short g_csr[EE];     // send ids grouped by recv (N<65536)
__device__ int    g_off[NN + 1];         // CSR offsets
__device__ int    g_deg[NN];             // histogram / scatter cursor
__device__ float4 g_pkA[NN];             // (x0,x1,x2,hs1); later (h4_0..2,hs4)
__device__ float  g_h2[NN * 64];         // h2 = relu(c@W1+b1)@W2 (no bias)
__device__ float  g_hsA[NN];             // src scalars (L3)
__device__ float  g_hdA[NN];             // dst scalars (L1, then L3)
__device__ float  g_hsB[NN];             // src scalars (L2, then L4)
__device__ float  g_hdB[NN];             // dst scalars (L2, then L4)
__device__ int    g_bsum[256];           // scan block sums
__device__ float  g_pool[BB * 64];
__device__ int    g_cnt[BB];
__device__ int    g_flags[2];            // [0] ei int64?  [1] batch int64?
__device__ float  g_w1s[3], g_w1d[3];
__device__ float  g_w3s[64], g_w3d[64];

__device__ __forceinline__ float lrelu_exp(float e) {
    e = e > 0.f ? e : 0.2f * e;
    return __expf(e);
}

// ---- packed f32x2 helpers (Blackwell FFMA2) ----
__device__ __forceinline__ unsigned long long pk2(float lo, float hi) {
    unsigned long long r;
    asm("mov.b64 %0, {%1, %2};" : "=l"(r) : "f"(lo), "f"(hi));
    return r;
}
__device__ __forceinline__ float2 upk2(unsigned long long v) {
    float lo, hi;
    asm("mov.b64 {%0, %1}, %2;" : "=f"(lo), "=f"(hi) : "l"(v));
    return make_float2(lo, hi);
}
__device__ __forceinline__ unsigned long long ffma2(
        unsigned long long a, unsigned long long b, unsigned long long c) {
    unsigned long long d;
    asm("fma.rn.f32x2 %0, %1, %2, %3;" : "=l"(d) : "l"(a), "l"(b), "l"(c));
    return d;
}
__device__ __forceinline__ unsigned long long add2(
        unsigned long long a, unsigned long long b) {
    unsigned long long d;
    asm("add.rn.f32x2 %0, %1, %2;" : "=l"(d) : "l"(a), "l"(b));
    return d;
}

// ---------------- the single kernel, phase-dispatched ----------------
// P0 init+detect+proj (197)   P1 hist (3125)     P2 scan1 (196)
// P3 scan2 (1)                P4 scan3+dots1+pack (196)
// P5 scatter (3125)           P6 aggL1 + h2 matvec + dots2 (6250)
// P7 aggL2 (64-payload) + pool + dots3 (6250)
// P8 aggL3 + dots4 (6250)     P9 aggL4->recon + classifier (6258)
__global__ void __launch_bounds__(256) gat_kernel(KParams p) {
    __shared__ float sf[1088];
    int* si = (int*)sf;
    const int t = threadIdx.x;
    const int b = blockIdx.x;
    const int ph = p.phase;

    if (ph == 0) {                       // ---- init + detect + proj ----
        if (b < 196) {
            int i = b * 256 + t;
            if (i < NN) g_deg[i] = 0;
            if (i < BB * 64) g_pool[i] = 0.f;
            if (i < BB) g_cnt[i] = 0;
            if (b == 0 && t < 64) {
                int lane = t & 31;
                int nz = 0;
                if (t < 32) {
                    for (int k = lane; k < 128; k += 32) nz |= p.ei[2 * k + 1];
                } else {
                    for (int k = lane; k < 128; k += 32) nz |= p.batch[NN - 256 + 2 * k + 1];
                }
                #pragma unroll
                for (int o = 16; o; o >>= 1) nz |= __shfl_xor_sync(0xffffffffu, nz, o);
                if (lane == 0) g_flags[t < 32 ? 0 : 1] = (nz == 0) ? 1 : 0;
            }
        } else {                         // block 196: projections (w3, w1)
            if (t < 64) {
                float s = 0.f, d = 0.f;
                for (int k = 0; k < 128; k++) {
                    float w = p.W3[t * 128 + k];
                    s = fmaf(w, p.a3s[k], s);
                    d = fmaf(w, p.a3d[k], d);
                }
                g_w3s[t] = s; g_w3d[t] = d;
            } else if (t < 67) {
                int i = t - 64;
                float s = 0.f;
                for (int k = 0; k < 128; k++) s = fmaf(p.W1[i * 128 + k], p.a1s[k], s);
                g_w1s[i] = s;
            } else if (t < 70) {
                int i = t - 67;
                float d = 0.f;
                for (int k = 0; k < 128; k++) d = fmaf(p.W1[i * 128 + k], p.a1d[k], d);
                g_w1d[i] = d;
            }
        }
    } else if (ph == 1) {                // ---- degree histogram ----
        int e = b * 256 + t;
        if (e < EE) {
            int r = g_flags[0] ? (int)((const long long*)p.ei)[(size_t)EE + e]
                               : p.ei[EE + e];
            atomicAdd(&g_deg[r], 1);
        }
    } else if (ph == 2) {                // ---- scan part 1 ----
        int i = b * 256 + t;
        int v = (i < NN) ? g_deg[i] : 0;
        si[t] = v;
        __syncthreads();
        #pragma unroll
        for (int d = 1; d < 256; d <<= 1) {
            int tv = (t >= d) ? si[t - d] : 0;
            __syncthreads();
            si[t] += tv;
            __syncthreads();
        }
        if (i < NN) g_off[i] = si[t] - v;
        if (t == 255) g_bsum[b] = si[255];
    } else if (ph == 3) {                // ---- scan part 2 ----
        int v = (t < 196) ? g_bsum[t] : 0;
        si[t] = v;
        __syncthreads();
        #pragma unroll
        for (int d = 1; d < 256; d <<= 1) {
            int tv = (t >= d) ? si[t - d] : 0;
            __syncthreads();
            si[t] += tv;
            __syncthreads();
        }
        if (t < 196) g_bsum[t] = si[t] - v;
    } else if (ph == 4) {                // ---- scan3 + dots1 + pack x ----
        int i = b * 256 + t;
        if (i < NN) {
            g_off[i] += g_bsum[b];
            g_deg[i] = 0;
            float x0 = p.x[i * 3 + 0], x1 = p.x[i * 3 + 1], x2 = p.x[i * 3 + 2];
            float hs = x0 * g_w1s[0] + x1 * g_w1s[1] + x2 * g_w1s[2];
            g_pkA[i] = make_float4(x0, x1, x2, hs);
            g_hdA[i] = x0 * g_w1d[0] + x1 * g_w1d[1] + x2 * g_w1d[2];
        }
        if (i == 0) g_off[NN] = EE;
    } else if (ph == 5) {                // ---- scatter to CSR ----
        int e = b * 256 + t;
        if (e < EE) {
            int r, s;
            if (g_flags[0]) {
                r = (int)((const long long*)p.ei)[(size_t)EE + e];
                s = (int)((const long long*)p.ei)[e];
            } else {
                r = p.ei[EE + e];
                s = p.ei[e];
            }
            int pos = g_off[r] + atomicAdd(&g_deg[r], 1);
            g_csr[pos] = (unsigned short)s;
        }
    } else if (ph == 6) {                // ---- aggL1 -> c, h2 = z@W2, dots2 ----
        int gw = (b * 256 + t) >> 5;
        int wid = (t >> 5) & 7;
        int lane = t & 31;
        if (gw < NN) {
            float* zsh = &sf[wid * 128];
            int beg = g_off[gw], end = g_off[gw + 1];
            float hdi = g_hdA[gw];
            float s = 0.f, a0 = 0.f, a1 = 0.f, a2 = 0.f;
            for (int j = beg + lane; j < end; j += 32) {
                int sn = g_csr[j];
                float4 pk = g_pkA[sn];               // one 16B gather: x + hs
                float w = lrelu_exp(pk.w + hdi);
                s += w;
                a0 = fmaf(w, pk.x, a0);
                a1 = fmaf(w, pk.y, a1);
                a2 = fmaf(w, pk.z, a2);
            }
            #pragma unroll
            for (int o = 16; o; o >>= 1) {
                s  += __shfl_xor_sync(0xffffffffu, s, o);
                a0 += __shfl_xor_sync(0xffffffffu, a0, o);
                a1 += __shfl_xor_sync(0xffffffffu, a1, o);
                a2 += __shfl_xor_sync(0xffffffffu, a2, o);
            }
            float4 pks = g_pkA[gw];                  // self loop
            float ws = lrelu_exp(pks.w + hdi);
            s += ws;
            a0 = fmaf(ws, pks.x, a0);
            a1 = fmaf(ws, pks.y, a1);
            a2 = fmaf(ws, pks.z, a2);
            float inv = 1.f / s;
            float c0 = a0 * inv, c1 = a1 * inv, c2 = a2 * inv;
            // z = relu(c@W1 + b1) in smem (4 dims per lane)
            int k0 = lane * 4;
            float4 w0 = *(const float4*)&p.W1[0 * 128 + k0];
            float4 w1 = *(const float4*)&p.W1[1 * 128 + k0];
            float4 w2 = *(const float4*)&p.W1[2 * 128 + k0];
            float4 bb = *(const float4*)&p.b1[k0];
            zsh[k0 + 0] = fmaxf(fmaf(c0, w0.x, fmaf(c1, w1.x, fmaf(c2, w2.x, bb.x))), 0.f);
            zsh[k0 + 1] = fmaxf(fmaf(c0, w0.y, fmaf(c1, w1.y, fmaf(c2, w2.y, bb.y))), 0.f);
            zsh[k0 + 2] = fmaxf(fmaf(c0, w0.z, fmaf(c1, w1.z, fmaf(c2, w2.z, bb.z))), 0.f);
            zsh[k0 + 3] = fmaxf(fmaf(c0, w0.w, fmaf(c1, w1.w, fmaf(c2, w2.w, bb.w))), 0.f);
            __syncwarp();
            // h2 = z @ W2  (4 outputs/lane, split-k halves, packed f32x2 FMA)
            int out4 = (lane & 15) * 4;
            int khalf = (lane >> 4) * 64;
            unsigned long long accA = 0ULL, accB = 0ULL;
            for (int kk = 0; kk < 64; kk++) {
                float zk = zsh[khalf + kk];
                unsigned long long zz = pk2(zk, zk);
                ulonglong2 wv = *(const ulonglong2*)&p.W2[(khalf + kk) * 64 + out4];
                accA = ffma2(zz, wv.x, accA);
                accB = ffma2(zz, wv.y, accB);
            }
            unsigned long long oA = __shfl_down_sync(0xffffffffu, accA, 16);
            unsigned long long oB = __shfl_down_sync(0xffffffffu, accB, 16);
            accA = add2(accA, oA);
            accB = add2(accB, oB);
            float ss = 0.f, dd = 0.f;
            if (lane < 16) {
                float2 lo = upk2(accA), hi = upk2(accB);
                float4 h2v = make_float4(lo.x, lo.y, hi.x, hi.y);
                *(float4*)&g_h2[(size_t)gw * 64 + out4] = h2v;
                float4 s4 = *(const float4*)&p.a2s[out4];
                float4 d4 = *(const float4*)&p.a2d[out4];
                ss = h2v.x * s4.x + h2v.y * s4.y + h2v.z * s4.z + h2v.w * s4.w;
                dd = h2v.x * d4.x + h2v.y * d4.y + h2v.z * d4.z + h2v.w * d4.w;
            }
            #pragma unroll
            for (int o = 16; o; o >>= 1) {
                ss += __shfl_xor_sync(0xffffffffu, ss, o);
                dd += __shfl_xor_sync(0xffffffffu, dd, o);
            }
            if (lane == 0) { g_hsB[gw] = ss; g_hdB[gw] = dd; }
        }
    } else if (ph == 7) {                // ---- aggL2 (64-payload) + pool + dots3 ----
        int gw = (b * 256 + t) >> 5;
        int lane = t & 31;
        if (gw < NN) {
            int beg = g_off[gw], end = g_off[gw + 1];
            float hdi = g_hdB[gw];
            int m = lane * 2;
            float s = 0.f, ax = 0.f, ay = 0.f;
            for (int base = beg; base < end; base += 32) {
                int n = end - base; n = n < 32 ? n : 32;
                int sn_l = g_csr[base + (lane < n ? lane : n - 1)];  // coalesced stage
                float hs_l = g_hsB[sn_l];                            // parallel gather
                for (int jj = 0; jj < n; jj++) {
                    int sn = __shfl_sync(0xffffffffu, sn_l, jj);
                    float hsv = __shfl_sync(0xffffffffu, hs_l, jj);
                    float w = lrelu_exp(hsv + hdi);
                    float2 v = *(const float2*)&g_h2[(size_t)sn * 64 + m];
                    s += w;
                    ax = fmaf(w, v.x, ax);
                    ay = fmaf(w, v.y, ay);
                }
            }
            {   // self loop
                float w = lrelu_exp(g_hsB[gw] + hdi);
                float2 v = *(const float2*)&g_h2[(size_t)gw * 64 + m];
                s += w;
                ax = fmaf(w, v.x, ax);
                ay = fmaf(w, v.y, ay);
            }
            float inv = 1.f / s;
            float o0 = ax * inv + p.b2[m];
            float o1 = ay * inv + p.b2[m + 1];
            p.latent[(size_t)gw * 64 + m]     = o0;
            p.latent[(size_t)gw * 64 + m + 1] = o1;
            // pooling (latent in registers)
            int bi = g_flags[1] ? (int)((const long long*)p.batch)[gw] : p.batch[gw];
            atomicAdd(&g_pool[bi * 64 + m], o0);
            atomicAdd(&g_pool[bi * 64 + m + 1], o1);
            if (lane == 0) atomicAdd(&g_cnt[bi], 1);
            // dots3
            float ss = o0 * g_w3s[m] + o1 * g_w3s[m + 1];
            float dd = o0 * g_w3d[m] + o1 * g_w3d[m + 1];
            #pragma unroll
            for (int o = 16; o; o >>= 1) {
                ss += __shfl_xor_sync(0xffffffffu, ss, o);
                dd += __shfl_xor_sync(0xffffffffu, dd, o);
            }
            if (lane == 0) { g_hsA[gw] = ss; g_hdA[gw] = dd; }
        }
    } else if (ph == 8) {                // ---- aggL3 + dots4, pack ----
        int gw = (b * 256 + t) >> 5;
        int wid = (t >> 5) & 7;
        int lane = t & 31;
        if (gw < NN) {
            float* dsh = &sf[wid * 64];
            int beg = g_off[gw], end = g_off[gw + 1];
            float hdi = g_hdA[gw];
            int m = lane * 2;
            float s = 0.f, ax = 0.f, ay = 0.f;
            for (int base = beg; base < end; base += 32) {
                int n = end - base; n = n < 32 ? n : 32;
                int sn_l = g_csr[base + (lane < n ? lane : n - 1)];  // coalesced stage
                float hs_l = g_hsA[sn_l];                            // parallel gather
                for (int jj = 0; jj < n; jj++) {
                    int sn = __shfl_sync(0xffffffffu, sn_l, jj);
                    float hsv = __shfl_sync(0xffffffffu, hs_l, jj);
                    float w = lrelu_exp(hsv + hdi);
                    float2 v = *(const float2*)&p.latent[(size_t)sn * 64 + m];
                    s += w;
                    ax = fmaf(w, v.x, ax);
                    ay = fmaf(w, v.y, ay);
                }
            }
            {   // self loop
                float w = lrelu_exp(g_hsA[gw] + hdi);
                float2 v = *(const float2*)&p.latent[(size_t)gw * 64 + m];
                s += w;
                ax = fmaf(w, v.x, ax);
                ay = fmaf(w, v.y, ay);
            }
            float inv = 1.f / s;
            dsh[m] = ax * inv;
            dsh[m + 1] = ay * inv;
            __syncwarp();
            // z = relu(dbar@W3 + b3), 4 dims/lane, packed f32x2
            int k0 = lane * 4;
            float4 b3v = *(const float4*)&p.b3[k0];
            unsigned long long accA = pk2(b3v.x, b3v.y);
            unsigned long long accB = pk2(b3v.z, b3v.w);
            for (int i = 0; i < 64; i++) {
                float di = dsh[i];
                unsigned long long dpk = pk2(di, di);
                ulonglong2 wv = *(const ulonglong2*)&p.W3[i * 128 + k0];
                accA = ffma2(dpk, wv.x, accA);
                accB = ffma2(dpk, wv.y, accB);
            }
            float2 zlo = upk2(accA), zhi = upk2(accB);
            float q0 = fmaxf(zlo.x, 0.f), q1 = fmaxf(zlo.y, 0.f);
            float q2 = fmaxf(zhi.x, 0.f), q3 = fmaxf(zhi.y, 0.f);
            float a0 = q0 * p.W4[(k0 + 0) * 3 + 0] + q1 * p.W4[(k0 + 1) * 3 + 0]
                     + q2 * p.W4[(k0 + 2) * 3 + 0] + q3 * p.W4[(k0 + 3) * 3 + 0];
            float a1 = q0 * p.W4[(k0 + 0) * 3 + 1] + q1 * p.W4[(k0 + 1) * 3 + 1]
                     + q2 * p.W4[(k0 + 2) * 3 + 1] + q3 * p.W4[(k0 + 3) * 3 + 1];
            float a2 = q0 * p.W4[(k0 + 0) * 3 + 2] + q1 * p.W4[(k0 + 1) * 3 + 2]
                     + q2 * p.W4[(k0 + 2) * 3 + 2] + q3 * p.W4[(k0 + 3) * 3 + 2];
            #pragma unroll
            for (int o = 16; o; o >>= 1) {
                a0 += __shfl_xor_sync(0xffffffffu, a0, o);
                a1 += __shfl_xor_sync(0xffffffffu, a1, o);
                a2 += __shfl_xor_sync(0xffffffffu, a2, o);
            }
            if (lane == 0) {
                float hs4 = a0 * p.a4s[0] + a1 * p.a4s[1] + a2 * p.a4s[2];
                g_pkA[gw] = make_float4(a0, a1, a2, hs4);
                g_hdB[gw] = a0 * p.a4d[0] + a1 * p.a4d[1] + a2 * p.a4d[2];
            }
        }
    } else if (ph == 9) {                // ---- aggL4 -> recon, + classifier tail ----
        int lane = t & 31;
        if (b < 6250) {
            int gw = (b * 256 + t) >> 5;
            if (gw < NN) {
                int beg = g_off[gw], end = g_off[gw + 1];
                float hdi = g_hdB[gw];
                float s = 0.f, a0 = 0.f, a1 = 0.f, a2 = 0.f;
                for (int j = beg + lane; j < end; j += 32) {
                    int sn = g_csr[j];
                    float4 pk = g_pkA[sn];           // one 16B gather: h4 + hs4
                    float w = lrelu_exp(pk.w + hdi);
                    s += w;
                    a0 = fmaf(w, pk.x, a0);
                    a1 = fmaf(w, pk.y, a1);
                    a2 = fmaf(w, pk.z, a2);
                }
                #pragma unroll
                for (int o = 16; o; o >>= 1) {
                    s  += __shfl_xor_sync(0xffffffffu, s, o);
                    a0 += __shfl_xor_sync(0xffffffffu, a0, o);
                    a1 += __shfl_xor_sync(0xffffffffu, a1, o);
                    a2 += __shfl_xor_sync(0xffffffffu, a2, o);
                }
                float4 pks = g_pkA[gw];
                float ws = lrelu_exp(pks.w + hdi);
                s += ws;
                a0 = fmaf(ws, pks.x, a0);
                a1 = fmaf(ws, pks.y, a1);
                a2 = fmaf(ws, pks.z, a2);
                float inv = 1.f / s;
                if (lane == 0) {
                    p.recon[gw * 3 + 0] = a0 * inv + p.b4[0];
                    p.recon[gw * 3 + 1] = a1 * inv + p.b4[1];
                    p.recon[gw * 3 + 2] = a2 * inv + p.b4[2];
                }
            }
        } else {                         // classifier: blocks 6250..6257
            int wid = t >> 5;
            int g = (b - 6250) * 8 + wid;
            if (g < BB) {
                float* pp = &sf[wid * 64];
                float invc = 1.f / fmaxf((float)g_cnt[g], 1.f);
                pp[lane] = g_pool[g * 64 + lane] * invc;
                pp[lane + 32] = g_pool[g * 64 + lane + 32] * invc;
                __syncwarp();
                float z = p.bc1[lane];
                #pragma unroll 8
                for (int d = 0; d < 64; d++) z = fmaf(pp[d], p.Wc1[d * 32 + lane], z);
                z = fmaxf(z, 0.f);
                float o0 = z * p.Wc2[lane * 2 + 0];
                float o1 = z * p.Wc2[lane * 2 + 1];
                #pragma unroll
                for (int o = 16; o; o >>= 1) {
                    o0 += __shfl_xor_sync(0xffffffffu, o0, o);
                    o1 += __shfl_xor_sync(0xffffffffu, o1, o);
                }
                if (lane == 0) {
                    p.pred[g * 2 + 0] = o0 + p.bc2[0];
                    p.pred[g * 2 + 1] = o1 + p.bc2[1];
                }
            }
        }
    }
}

// ---------------- launcher ----------------
extern "C" void kernel_launch(void* const* d_in, const int* in_sizes, int n_in,
                              void* d_out, int out_size) {
    KParams p;
    p.x     = (const float*)d_in[0];
    p.ei    = (const int*)d_in[1];
    p.batch = (const int*)d_in[2];
    p.W1 = (const float*)d_in[3];  p.a1s = (const float*)d_in[4];
    p.a1d = (const float*)d_in[5]; p.b1  = (const float*)d_in[6];
    p.W2 = (const float*)d_in[7];  p.a2s = (const float*)d_in[8];
    p.a2d = (const float*)d_in[9]; p.b2  = (const float*)d_in[10];
    p.W3 = (const float*)d_in[11]; p.a3s = (const float*)d_in[12];
    p.a3d = (const float*)d_in[13];p.b3  = (const float*)d_in[14];
    p.W4 = (const float*)d_in[15]; p.a4s = (const float*)d_in[16];
    p.a4d = (const float*)d_in[17];p.b4  = (const float*)d_in[18];
    p.Wc1 = (const float*)d_in[19];p.bc1 = (const float*)d_in[20];
    p.Wc2 = (const float*)d_in[21];p.bc2 = (const float*)d_in[22];
    p.recon  = (float*)d_out;
    p.latent = (float*)d_out + 150000;
    p.pred   = (float*)d_out + 150000 + 3200000;

    const int nGrid = (NN + 255) / 256;          // 196
    const int eGrid = (EE + 255) / 256;          // 3125
    const int wGrid = (NN * 32 + 255) / 256;     // 6250

    p.phase = 0;  gat_kernel<<<nGrid + 1, 256>>>(p);  // init + detect + proj
    p.phase = 1;  gat_kernel<<<eGrid, 256>>>(p);      // histogram
    p.phase = 2;  gat_kernel<<<nGrid, 256>>>(p);      // scan (block)
    p.phase = 3;  gat_kernel<<<1, 256>>>(p);          // scan (sums)
    p.phase = 4;  gat_kernel<<<nGrid, 256>>>(p);      // scan (add) + dots1 + pack
    p.phase = 5;  gat_kernel<<<eGrid, 256>>>(p);      // scatter -> CSR
    p.phase = 6;  gat_kernel<<<wGrid, 256>>>(p);      // L1 agg + h2 + dots2
    p.phase = 7;  gat_kernel<<<wGrid, 256>>>(p);      // L2 agg + pool + dots3
    p.phase = 8;  gat_kernel<<<wGrid, 256>>>(p);      // L3 agg + dots4
    p.phase = 9;  gat_kernel<<<wGrid + 8, 256>>>(p);  // L4 agg -> recon + cls
}